// round 2
// baseline (speedup 1.0000x reference)
#include <cuda_runtime.h>
#include <cstdint>

// Problem constants (z: (64,13,128,128) fp32)
#define BB 64
#define CC 13
#define HH 128
#define WW 128
#define HWSZ (HH*WW)                  // 16384
#define NPIX (BB*HWSZ)                // 1,048,576
#define NTOT (CC*NPIX)                // 13,631,488

#define THREADS 256
#define VEC 4
#define NBLOCKS (NPIX / (THREADS*VEC))  // 1024
#define NACC 15                          // commit, ent, 13 channel p0 sums

// Deterministic scratch: per-block partial sums. Fully overwritten each launch.
__device__ float g_partials[NBLOCKS * 16];

__device__ __forceinline__ void proc_lane(float zv, float& q, float& commit_acc,
                                          float& ent_acc, float& p0_acc, int& idx) {
    bool pos = zv > 0.0f;
    q = pos ? 1.0f : -1.0f;
    float az = fabsf(zv);
    float d = 1.0f - az;
    commit_acc = fmaf(d, d, commit_acc);
    float a = 4.0f * az;                 // |l0 - l1|
    float e = __expf(-a);                // e^{-a}, a >= 0 so e in (0,1]
    float opE = 1.0f + e;
    float r = __fdividef(1.0f, opE);     // MUFU.RCP path
    float p_big = r;                     // sigmoid(a)
    float p_small = e * r;               // 1 - sigmoid(a)
    float L = __logf(opE);               // log(1+e) = log1p(e), e<=1 so accurate
    ent_acc += L + a * p_small;          // H(p)
    p0_acc += pos ? p_big : p_small;     // p0 = sigmoid(4z)
    idx = (idx << 1) | (pos ? 1 : 0);    // MSB = channel 0
}

__global__ void __launch_bounds__(THREADS)
lfq_main(const float* __restrict__ z, float* __restrict__ out) {
    float* zq      = out;                 // [0, NTOT)
    float* idx_out = out + NTOT + 2;      // [NTOT+2, NTOT+2+NPIX)  (8B-aligned only!)

    int tid = threadIdx.x;
    int g   = blockIdx.x * THREADS + tid;     // group of 4 pixels
    int pix = g * VEC;
    int b   = pix / HWSZ;
    int hw  = pix - b * HWSZ;                 // 4-aligned; block never straddles b
    size_t base = (size_t)b * (CC * HWSZ) + hw;

    float commit_acc = 0.0f, ent_acc = 0.0f;
    float ch_acc[CC];
    int idx0 = 0, idx1 = 0, idx2 = 0, idx3 = 0;

    #pragma unroll
    for (int c = 0; c < CC; c++) {
        float4 zv = *reinterpret_cast<const float4*>(z + base + (size_t)c * HWSZ);
        float4 qv;
        float ca = 0.0f;
        proc_lane(zv.x, qv.x, commit_acc, ent_acc, ca, idx0);
        proc_lane(zv.y, qv.y, commit_acc, ent_acc, ca, idx1);
        proc_lane(zv.z, qv.z, commit_acc, ent_acc, ca, idx2);
        proc_lane(zv.w, qv.w, commit_acc, ent_acc, ca, idx3);
        *reinterpret_cast<float4*>(zq + base + (size_t)c * HWSZ) = qv;
        ch_acc[c] = ca;
    }

    // idx_out is only 8-byte aligned (NTOT+2 ≡ 2 mod 4 elements) -> use float2 stores
    float2 iv0 = make_float2((float)idx0, (float)idx1);
    float2 iv1 = make_float2((float)idx2, (float)idx3);
    *reinterpret_cast<float2*>(idx_out + pix)     = iv0;
    *reinterpret_cast<float2*>(idx_out + pix + 2) = iv1;

    // ---- block reduction of 15 accumulators ----
    float vals[NACC];
    vals[0] = commit_acc;
    vals[1] = ent_acc;
    #pragma unroll
    for (int c = 0; c < CC; c++) vals[2 + c] = ch_acc[c];

    #pragma unroll
    for (int i = 0; i < NACC; i++) {
        #pragma unroll
        for (int o = 16; o; o >>= 1)
            vals[i] += __shfl_xor_sync(0xffffffffu, vals[i], o);
    }

    __shared__ float s[NACC];
    if (tid < NACC) s[tid] = 0.0f;
    __syncthreads();
    if ((tid & 31) == 0) {
        #pragma unroll
        for (int i = 0; i < NACC; i++) atomicAdd(&s[i], vals[i]);
    }
    __syncthreads();
    if (tid < NACC) g_partials[blockIdx.x * 16 + tid] = s[tid];
}

__global__ void __launch_bounds__(1024)
lfq_finalize(float* __restrict__ out) {
    int t = threadIdx.x;  // 1024 threads == NBLOCKS
    __shared__ float warp_sums[32];
    __shared__ float S[NACC];

    for (int i = 0; i < NACC; i++) {
        float v = g_partials[t * 16 + i];
        #pragma unroll
        for (int o = 16; o; o >>= 1) v += __shfl_xor_sync(0xffffffffu, v, o);
        if ((t & 31) == 0) warp_sums[t >> 5] = v;
        __syncthreads();
        if (t < 32) {
            float w = warp_sums[t];
            #pragma unroll
            for (int o = 16; o; o >>= 1) w += __shfl_xor_sync(0xffffffffu, w, o);
            if (t == 0) S[i] = w;
        }
        __syncthreads();
    }

    if (t == 0) {
        double commit = (double)S[0] / (double)NTOT * 1.25 * 0.1;
        double entropy = (double)S[1] / (double)NTOT;
        double mean_ent = 0.0;
        for (int c = 0; c < CC; c++) {
            double mp = (double)S[2 + c] / (double)NPIX;
            if (mp < 1e-12) mp = 1e-12;
            if (mp > 1.0 - 1e-12) mp = 1.0 - 1e-12;
            mean_ent += -(mp * log(mp) + (1.0 - mp) * log(1.0 - mp));
        }
        mean_ent /= (double)CC;
        out[NTOT]     = (float)commit;
        out[NTOT + 1] = (float)((entropy - mean_ent) * 0.1);
    }
}

extern "C" void kernel_launch(void* const* d_in, const int* in_sizes, int n_in,
                              void* d_out, int out_size) {
    const float* z = (const float*)d_in[0];
    float* out = (float*)d_out;
    lfq_main<<<NBLOCKS, THREADS>>>(z, out);
    lfq_finalize<<<1, 1024>>>(out);
}